// round 1
// baseline (speedup 1.0000x reference)
#include <cuda_runtime.h>
#include <math.h>

#define BATCH 8
#define CH    256
#define NPIX  4096   // 64*64

// Scratch (allocation-free rule: __device__ globals)
static __device__ float g_q[BATCH * CH * NPIX];
static __device__ float g_k[BATCH * CH * NPIX];
static __device__ float g_v[BATCH * CH * NPIX];
static __device__ float g_s[(size_t)BATCH * NPIX * NPIX];   // 537 MB scores/attn

// ---------------------------------------------------------------------------
// Kernel 1: QKV projections.  Y[b] = W * X[b] + bias, W:[256,256], X:[256,4096]
// 128x128 tile, kb=8, 256 threads, 8x8 microtile.
// ---------------------------------------------------------------------------
__global__ __launch_bounds__(256) void qkv_kernel(
    const float* __restrict__ x,
    const float* __restrict__ wq, const float* __restrict__ bq,
    const float* __restrict__ wk, const float* __restrict__ bk,
    const float* __restrict__ wv, const float* __restrict__ bv)
{
    const int which = blockIdx.z % 3;
    const int b     = blockIdx.z / 3;
    const float* W    = (which == 0) ? wq : (which == 1) ? wk : wv;
    const float* bias = (which == 0) ? bq : (which == 1) ? bk : bv;
    float*       Yg   = (which == 0) ? g_q : (which == 1) ? g_k : g_v;

    const float* X = x  + (size_t)b * CH * NPIX;
    float*       Y = Yg + (size_t)b * CH * NPIX;
    const int m0 = blockIdx.y * 128;
    const int n0 = blockIdx.x * 128;

    __shared__ __align__(16) float As[8][132];
    __shared__ __align__(16) float Bs[8][132];

    const int tid = threadIdx.x;
    const int tn = tid & 15, tm = tid >> 4;

    float acc[8][8] = {};

    for (int k0 = 0; k0 < CH; k0 += 8) {
        #pragma unroll
        for (int t = tid; t < 1024; t += 256) {
            int kk = t & 7, mm = t >> 3;
            As[kk][mm] = W[(m0 + mm) * CH + k0 + kk];
        }
        #pragma unroll
        for (int t = tid; t < 1024; t += 256) {
            int nn = t & 127, kk = t >> 7;
            Bs[kk][nn] = X[(size_t)(k0 + kk) * NPIX + n0 + nn];
        }
        __syncthreads();
        #pragma unroll
        for (int kk = 0; kk < 8; ++kk) {
            float a[8], bb[8];
            *(float4*)&a[0]  = *(const float4*)&As[kk][tm * 8];
            *(float4*)&a[4]  = *(const float4*)&As[kk][tm * 8 + 4];
            *(float4*)&bb[0] = *(const float4*)&Bs[kk][tn * 8];
            *(float4*)&bb[4] = *(const float4*)&Bs[kk][tn * 8 + 4];
            #pragma unroll
            for (int i = 0; i < 8; i++)
                #pragma unroll
                for (int j = 0; j < 8; j++)
                    acc[i][j] = fmaf(a[i], bb[j], acc[i][j]);
        }
        __syncthreads();
    }

    #pragma unroll
    for (int i = 0; i < 8; i++) {
        float bi = bias[m0 + tm * 8 + i];
        float4* p = (float4*)&Y[(size_t)(m0 + tm * 8 + i) * NPIX + n0 + tn * 8];
        p[0] = make_float4(acc[i][0] + bi, acc[i][1] + bi, acc[i][2] + bi, acc[i][3] + bi);
        p[1] = make_float4(acc[i][4] + bi, acc[i][5] + bi, acc[i][6] + bi, acc[i][7] + bi);
    }
}

// ---------------------------------------------------------------------------
// Kernel 2: scores S[b,i,j] = sum_c Q[b,c,i] * K[b,c,j].  K-dim = C = 256.
// ---------------------------------------------------------------------------
__global__ __launch_bounds__(256) void scores_kernel()
{
    const int b = blockIdx.z;
    const float* Q  = g_q + (size_t)b * CH * NPIX;
    const float* Kp = g_k + (size_t)b * CH * NPIX;
    float*       S  = g_s + (size_t)b * NPIX * NPIX;
    const int i0 = blockIdx.y * 128;
    const int j0 = blockIdx.x * 128;

    __shared__ __align__(16) float As[8][132];
    __shared__ __align__(16) float Bs[8][132];

    const int tid = threadIdx.x;
    const int tn = tid & 15, tm = tid >> 4;

    float acc[8][8] = {};

    for (int k0 = 0; k0 < CH; k0 += 8) {
        #pragma unroll
        for (int t = tid; t < 1024; t += 256) {
            int mm = t & 127, kk = t >> 7;
            As[kk][mm] = Q[(size_t)(k0 + kk) * NPIX + i0 + mm];
        }
        #pragma unroll
        for (int t = tid; t < 1024; t += 256) {
            int nn = t & 127, kk = t >> 7;
            Bs[kk][nn] = Kp[(size_t)(k0 + kk) * NPIX + j0 + nn];
        }
        __syncthreads();
        #pragma unroll
        for (int kk = 0; kk < 8; ++kk) {
            float a[8], bb[8];
            *(float4*)&a[0]  = *(const float4*)&As[kk][tm * 8];
            *(float4*)&a[4]  = *(const float4*)&As[kk][tm * 8 + 4];
            *(float4*)&bb[0] = *(const float4*)&Bs[kk][tn * 8];
            *(float4*)&bb[4] = *(const float4*)&Bs[kk][tn * 8 + 4];
            #pragma unroll
            for (int i = 0; i < 8; i++)
                #pragma unroll
                for (int j = 0; j < 8; j++)
                    acc[i][j] = fmaf(a[i], bb[j], acc[i][j]);
        }
        __syncthreads();
    }

    #pragma unroll
    for (int i = 0; i < 8; i++) {
        float4* p = (float4*)&S[(size_t)(i0 + tm * 8 + i) * NPIX + j0 + tn * 8];
        p[0] = make_float4(acc[i][0], acc[i][1], acc[i][2], acc[i][3]);
        p[1] = make_float4(acc[i][4], acc[i][5], acc[i][6], acc[i][7]);
    }
}

// ---------------------------------------------------------------------------
// Kernel 3: row softmax over g_s. One block (256 thr) per row of 4096.
// Values held in registers (16/thread): single read, single write.
// ---------------------------------------------------------------------------
__global__ __launch_bounds__(256) void softmax_kernel()
{
    float* row = g_s + (size_t)blockIdx.x * NPIX;
    const int tid = threadIdx.x;

    float v[16];
    float mx = -1e30f;
    #pragma unroll
    for (int i = 0; i < 16; i++) {
        v[i] = row[tid + 256 * i];
        mx = fmaxf(mx, v[i]);
    }

    __shared__ float red[8];
    #pragma unroll
    for (int o = 16; o > 0; o >>= 1)
        mx = fmaxf(mx, __shfl_xor_sync(0xffffffffu, mx, o));
    if ((tid & 31) == 0) red[tid >> 5] = mx;
    __syncthreads();
    float bm = red[0];
    #pragma unroll
    for (int i = 1; i < 8; i++) bm = fmaxf(bm, red[i]);
    __syncthreads();

    float sum = 0.f;
    #pragma unroll
    for (int i = 0; i < 16; i++) {
        v[i] = expf(v[i] - bm);
        sum += v[i];
    }
    #pragma unroll
    for (int o = 16; o > 0; o >>= 1)
        sum += __shfl_xor_sync(0xffffffffu, sum, o);
    if ((tid & 31) == 0) red[tid >> 5] = sum;
    __syncthreads();
    float tot = 0.f;
    #pragma unroll
    for (int i = 0; i < 8; i++) tot += red[i];
    float inv = 1.0f / tot;

    #pragma unroll
    for (int i = 0; i < 16; i++)
        row[tid + 256 * i] = v[i] * inv;
}

// ---------------------------------------------------------------------------
// Kernel 4: out[b,c,i] = sum_j V[b,c,j] * attn[b,i,j].  K-dim = N = 4096.
// ---------------------------------------------------------------------------
__global__ __launch_bounds__(256) void out_kernel(float* __restrict__ O)
{
    const int b = blockIdx.z;
    const float* V = g_v + (size_t)b * CH * NPIX;
    const float* A = g_s + (size_t)b * NPIX * NPIX;
    float*       Ob = O + (size_t)b * CH * NPIX;
    const int m0 = blockIdx.y * 128;   // channel tile
    const int n0 = blockIdx.x * 128;   // query-pixel tile

    __shared__ __align__(16) float As[8][132];
    __shared__ __align__(16) float Bs[8][132];

    const int tid = threadIdx.x;
    const int tn = tid & 15, tm = tid >> 4;

    float acc[8][8] = {};

    for (int j0 = 0; j0 < NPIX; j0 += 8) {
        #pragma unroll
        for (int t = tid; t < 1024; t += 256) {
            int kk = t & 7, mm = t >> 3;
            As[kk][mm] = V[(size_t)(m0 + mm) * NPIX + j0 + kk];
        }
        #pragma unroll
        for (int t = tid; t < 1024; t += 256) {
            int kk = t & 7, nn = t >> 3;
            Bs[kk][nn] = A[(size_t)(n0 + nn) * NPIX + j0 + kk];
        }
        __syncthreads();
        #pragma unroll
        for (int kk = 0; kk < 8; ++kk) {
            float a[8], bb[8];
            *(float4*)&a[0]  = *(const float4*)&As[kk][tm * 8];
            *(float4*)&a[4]  = *(const float4*)&As[kk][tm * 8 + 4];
            *(float4*)&bb[0] = *(const float4*)&Bs[kk][tn * 8];
            *(float4*)&bb[4] = *(const float4*)&Bs[kk][tn * 8 + 4];
            #pragma unroll
            for (int i = 0; i < 8; i++)
                #pragma unroll
                for (int j = 0; j < 8; j++)
                    acc[i][j] = fmaf(a[i], bb[j], acc[i][j]);
        }
        __syncthreads();
    }

    #pragma unroll
    for (int i = 0; i < 8; i++) {
        float4* p = (float4*)&Ob[(size_t)(m0 + tm * 8 + i) * NPIX + n0 + tn * 8];
        p[0] = make_float4(acc[i][0], acc[i][1], acc[i][2], acc[i][3]);
        p[1] = make_float4(acc[i][4], acc[i][5], acc[i][6], acc[i][7]);
    }
}

// ---------------------------------------------------------------------------
extern "C" void kernel_launch(void* const* d_in, const int* in_sizes, int n_in,
                              void* d_out, int out_size)
{
    const float* x  = (const float*)d_in[0];
    const float* wq = (const float*)d_in[1];
    const float* bq = (const float*)d_in[2];
    const float* wk = (const float*)d_in[3];
    const float* bk = (const float*)d_in[4];
    const float* wv = (const float*)d_in[5];
    const float* bv = (const float*)d_in[6];
    float* out = (float*)d_out;

    dim3 blk(256);
    qkv_kernel   <<<dim3(NPIX / 128, CH / 128, BATCH * 3), blk>>>(x, wq, bq, wk, bk, wv, bv);
    scores_kernel<<<dim3(NPIX / 128, NPIX / 128, BATCH),   blk>>>();
    softmax_kernel<<<dim3(BATCH * NPIX), blk>>>();
    out_kernel   <<<dim3(NPIX / 128, CH / 128, BATCH),     blk>>>(out);
}

// round 3
// speedup vs baseline: 2.9279x; 2.9279x over previous
#include <cuda_runtime.h>
#include <cuda_bf16.h>
#include <math.h>
#include <stdint.h>

#define BATCH 8
#define CH    256
#define NPIX  4096

// Packed split-bf16: u32 = bf16(hi) | bf16(lo)<<16, value ~= hi + lo
static __device__ uint32_t g_wp[3 * CH * CH];                  // packed wq|wk|wv
static __device__ uint32_t g_xt[(size_t)BATCH * NPIX * CH];    // x^T  [b][n][c]
static __device__ uint32_t g_qt[(size_t)BATCH * NPIX * CH];    // Q^T  [b][n][c]
static __device__ uint32_t g_kt[(size_t)BATCH * NPIX * CH];    // K^T  [b][n][c]
static __device__ uint32_t g_vp[(size_t)BATCH * CH * NPIX];    // V    [b][c][n]
static __device__ float    g_s [(size_t)BATCH * NPIX * NPIX];  // scores fp32
static __device__ uint32_t g_ap[(size_t)BATCH * NPIX * NPIX];  // attn packed

__device__ __forceinline__ uint32_t smem_u32(const void* p) {
    uint32_t a;
    asm("{ .reg .u64 t; cvta.to.shared.u64 t, %1; cvt.u32.u64 %0, t; }" : "=r"(a) : "l"(p));
    return a;
}
__device__ __forceinline__ uint32_t pack_split(float v) {
    __nv_bfloat16 h = __float2bfloat16(v);
    float r = v - __bfloat162float(h);
    __nv_bfloat16 l = __float2bfloat16(r);
    return (uint32_t)__bfloat16_as_ushort(h) | ((uint32_t)__bfloat16_as_ushort(l) << 16);
}
__device__ __forceinline__ void cp16(uint32_t saddr, const uint32_t* g) {
    uint64_t ga;
    asm("cvta.to.global.u64 %0, %1;" : "=l"(ga) : "l"(g));
    asm volatile("cp.async.cg.shared.global [%0], [%1], 16;" :: "r"(saddr), "l"(ga));
}
#define CP_COMMIT() asm volatile("cp.async.commit_group;" ::: "memory")
#define CP_WAIT1()  asm volatile("cp.async.wait_group 1;"  ::: "memory")
#define LDS64(a, b, addr) \
    asm volatile("ld.shared.v2.u32 {%0,%1}, [%2];" : "=r"(a), "=r"(b) : "r"(addr))
#define MMA(d, a, b0, b1)                                                         \
    asm volatile("mma.sync.aligned.m16n8k16.row.col.f32.bf16.bf16.f32 "           \
        "{%0,%1,%2,%3}, {%4,%5,%6,%7}, {%8,%9}, {%0,%1,%2,%3};"                   \
        : "+f"((d)[0]), "+f"((d)[1]), "+f"((d)[2]), "+f"((d)[3])                  \
        : "r"((a)[0]), "r"((a)[1]), "r"((a)[2]), "r"((a)[3]), "r"(b0), "r"(b1))

// ---------------------------------------------------------------------------
// GEMM: D[M,N] = A[M,K] * B[N,K]^T  with packed split-bf16 A,B (3-MMA emul).
// CTA 128x256, BK=32, 8 warps (2x4), warp tile 64x64. Double-buffered cp.async.
// MODE: 0 = fp32 out; 1 = packed out + bias[col]; 2 = packed out + bias[row]
// ---------------------------------------------------------------------------
#define BM 128
#define BN 256
#define BK 32
#define A_U32S  (BM * 40)                 // 5120 u32
#define B_U32S  (BN * 40)                 // 10240 u32
#define A_BYTES (A_U32S * 4)              // 20480
#define BUF_BYTES ((A_U32S + B_U32S) * 4) // 61440
#define GEMM_SMEM (2 * BUF_BYTES)         // 122880

__device__ __forceinline__ void load_tiles(const uint32_t* __restrict__ Ag, int lda,
                                           const uint32_t* __restrict__ Bg, int ldb,
                                           uint32_t sbase, int tid) {
    #pragma unroll
    for (int i = 0; i < 4; i++) {
        int t = i * 256 + tid;
        int row = t >> 3, q = t & 7;
        cp16(sbase + (uint32_t)(row * 40 + q * 4) * 4, Ag + (size_t)row * lda + q * 4);
    }
    #pragma unroll
    for (int i = 0; i < 8; i++) {
        int t = i * 256 + tid;
        int row = t >> 3, q = t & 7;
        cp16(sbase + A_BYTES + (uint32_t)(row * 40 + q * 4) * 4, Bg + (size_t)row * ldb + q * 4);
    }
}

__device__ __forceinline__ void compute_tile(uint32_t sa, int lane, int wm, int wn,
                                             float (&acc)[4][8][4]) {
    uint32_t sb = sa + A_BYTES;
    #pragma unroll
    for (int ks = 0; ks < 2; ks++) {
        const int kc = ks * 16 + (lane & 3) * 2;   // u32 col within tile
        uint32_t ah[4][4], al[4][4];
        #pragma unroll
        for (int mt = 0; mt < 4; mt++) {
            int r = wm * 64 + mt * 16 + (lane >> 2);
            uint32_t x0, x1, y0, y1, x2, x3, y2, y3;
            LDS64(x0, x1, sa + (uint32_t)(r * 40 + kc) * 4);
            LDS64(y0, y1, sa + (uint32_t)((r + 8) * 40 + kc) * 4);
            LDS64(x2, x3, sa + (uint32_t)(r * 40 + kc + 8) * 4);
            LDS64(y2, y3, sa + (uint32_t)((r + 8) * 40 + kc + 8) * 4);
            ah[mt][0] = __byte_perm(x0, x1, 0x5410); al[mt][0] = __byte_perm(x0, x1, 0x7632);
            ah[mt][1] = __byte_perm(y0, y1, 0x5410); al[mt][1] = __byte_perm(y0, y1, 0x7632);
            ah[mt][2] = __byte_perm(x2, x3, 0x5410); al[mt][2] = __byte_perm(x2, x3, 0x7632);
            ah[mt][3] = __byte_perm(y2, y3, 0x5410); al[mt][3] = __byte_perm(y2, y3, 0x7632);
        }
        #pragma unroll
        for (int nt = 0; nt < 8; nt++) {
            int r = wn * 64 + nt * 8 + (lane >> 2);
            uint32_t u0, u1, u2, u3;
            LDS64(u0, u1, sb + (uint32_t)(r * 40 + kc) * 4);
            LDS64(u2, u3, sb + (uint32_t)(r * 40 + kc + 8) * 4);
            uint32_t bh0 = __byte_perm(u0, u1, 0x5410), bh1 = __byte_perm(u2, u3, 0x5410);
            uint32_t bl0 = __byte_perm(u0, u1, 0x7632), bl1 = __byte_perm(u2, u3, 0x7632);
            #pragma unroll
            for (int mt = 0; mt < 4; mt++) {
                MMA(acc[mt][nt], ah[mt], bh0, bh1);
                MMA(acc[mt][nt], ah[mt], bl0, bl1);
                MMA(acc[mt][nt], al[mt], bh0, bh1);
            }
        }
    }
}

template<int MODE>
__global__ __launch_bounds__(256)
void gemm_kernel(const uint32_t* __restrict__ A, int lda, size_t sA,
                 const uint32_t* __restrict__ B, int ldb, size_t sB,
                 void* __restrict__ Dv, int ldd, size_t sD,
                 const float* __restrict__ bias, int K)
{
    extern __shared__ __align__(16) uint32_t smraw[];
    const uint32_t smbase = smem_u32(smraw);
    const int tid = threadIdx.x;
    const int lane = tid & 31, wid = tid >> 5;
    const int wm = wid >> 2, wn = wid & 3;
    const int z = blockIdx.z;
    const int bm = blockIdx.y * BM, bn = blockIdx.x * BN;

    A += (size_t)z * sA + (size_t)bm * lda;
    B += (size_t)z * sB + (size_t)bn * ldb;

    float acc[4][8][4];
    #pragma unroll
    for (int i = 0; i < 4; i++)
        #pragma unroll
        for (int j = 0; j < 8; j++)
            #pragma unroll
            for (int v = 0; v < 4; v++) acc[i][j][v] = 0.f;

    const int S = K / BK;
    load_tiles(A, lda, B, ldb, smbase, tid);
    CP_COMMIT();
    #pragma unroll 1
    for (int s = 0; s < S; s++) {
        if (s + 1 < S)
            load_tiles(A + (s + 1) * BK, lda, B + (s + 1) * BK, ldb,
                       smbase + (uint32_t)((s + 1) & 1) * BUF_BYTES, tid);
        CP_COMMIT();
        CP_WAIT1();
        __syncthreads();
        compute_tile(smbase + (uint32_t)(s & 1) * BUF_BYTES, lane, wm, wn, acc);
        __syncthreads();
    }

    // Epilogue
    #pragma unroll
    for (int nt = 0; nt < 8; nt++) {
        int col = bn + wn * 64 + nt * 8 + (lane & 3) * 2;
        float bc0 = 0.f, bc1 = 0.f;
        if (MODE == 1) { bc0 = bias[col]; bc1 = bias[col + 1]; }
        #pragma unroll
        for (int mt = 0; mt < 4; mt++) {
            int r0 = bm + wm * 64 + mt * 16 + (lane >> 2);
            if (MODE == 0) {
                float* D = (float*)Dv + (size_t)z * sD;
                *(float2*)&D[(size_t)r0 * ldd + col] =
                    make_float2(acc[mt][nt][0], acc[mt][nt][1]);
                *(float2*)&D[(size_t)(r0 + 8) * ldd + col] =
                    make_float2(acc[mt][nt][2], acc[mt][nt][3]);
            } else {
                uint32_t* D = (uint32_t*)Dv + (size_t)z * sD;
                float br0 = bc0, br1 = bc1, br2 = bc0, br3 = bc1;
                if (MODE == 2) {
                    float b0 = bias[r0], b8 = bias[r0 + 8];
                    br0 = b0; br1 = b0; br2 = b8; br3 = b8;
                }
                *(uint2*)&D[(size_t)r0 * ldd + col] =
                    make_uint2(pack_split(acc[mt][nt][0] + br0),
                               pack_split(acc[mt][nt][1] + br1));
                *(uint2*)&D[(size_t)(r0 + 8) * ldd + col] =
                    make_uint2(pack_split(acc[mt][nt][2] + br2),
                               pack_split(acc[mt][nt][3] + br3));
            }
        }
    }
}

// ---------------------------------------------------------------------------
// Packing kernels
// ---------------------------------------------------------------------------
__global__ __launch_bounds__(256) void pack_w_kernel(
    const float* __restrict__ wq, const float* __restrict__ wk,
    const float* __restrict__ wv)
{
    int i = blockIdx.x * 256 + threadIdx.x;      // 65536 total
    g_wp[i]               = pack_split(wq[i]);
    g_wp[CH * CH + i]     = pack_split(wk[i]);
    g_wp[2 * CH * CH + i] = pack_split(wv[i]);
}

__global__ __launch_bounds__(256) void pack_xt_kernel(const float* __restrict__ x)
{
    __shared__ float t[32][33];
    const int b = blockIdx.z;
    const int n0 = blockIdx.x * 32, c0 = blockIdx.y * 32;
    const int tx = threadIdx.x, ty = threadIdx.y;   // 32 x 8
    const float* xb = x + (size_t)b * CH * NPIX;
    #pragma unroll
    for (int i = 0; i < 4; i++)
        t[ty * 4 + i][tx] = xb[(size_t)(c0 + ty * 4 + i) * NPIX + n0 + tx];
    __syncthreads();
    uint32_t* xt = g_xt + (size_t)b * NPIX * CH;
    #pragma unroll
    for (int i = 0; i < 4; i++)
        xt[(size_t)(n0 + ty * 4 + i) * CH + c0 + tx] = pack_split(t[tx][ty * 4 + i]);
}

// ---------------------------------------------------------------------------
// Softmax: fp32 scores row -> packed split-bf16 attn row
// ---------------------------------------------------------------------------
__global__ __launch_bounds__(256) void softmax_kernel()
{
    const float* row = g_s + (size_t)blockIdx.x * NPIX;
    uint32_t* orow = g_ap + (size_t)blockIdx.x * NPIX;
    const int tid = threadIdx.x;

    float v[16];
    float mx = -1e30f;
    #pragma unroll
    for (int i = 0; i < 16; i++) {
        v[i] = row[tid + 256 * i];
        mx = fmaxf(mx, v[i]);
    }
    __shared__ float red[8];
    #pragma unroll
    for (int o = 16; o > 0; o >>= 1)
        mx = fmaxf(mx, __shfl_xor_sync(0xffffffffu, mx, o));
    if ((tid & 31) == 0) red[tid >> 5] = mx;
    __syncthreads();
    float bm = red[0];
    #pragma unroll
    for (int i = 1; i < 8; i++) bm = fmaxf(bm, red[i]);
    __syncthreads();

    float sum = 0.f;
    #pragma unroll
    for (int i = 0; i < 16; i++) {
        v[i] = expf(v[i] - bm);
        sum += v[i];
    }
    #pragma unroll
    for (int o = 16; o > 0; o >>= 1)
        sum += __shfl_xor_sync(0xffffffffu, sum, o);
    if ((tid & 31) == 0) red[tid >> 5] = sum;
    __syncthreads();
    float tot = 0.f;
    #pragma unroll
    for (int i = 0; i < 8; i++) tot += red[i];
    float inv = 1.0f / tot;

    #pragma unroll
    for (int i = 0; i < 16; i++)
        orow[tid + 256 * i] = pack_split(v[i] * inv);
}

// ---------------------------------------------------------------------------
extern "C" void kernel_launch(void* const* d_in, const int* in_sizes, int n_in,
                              void* d_out, int out_size)
{
    const float* x  = (const float*)d_in[0];
    const float* wq = (const float*)d_in[1];
    const float* bq = (const float*)d_in[2];
    const float* wk = (const float*)d_in[3];
    const float* bk = (const float*)d_in[4];
    const float* wv = (const float*)d_in[5];
    const float* bv = (const float*)d_in[6];
    float* out = (float*)d_out;

    void *pwp, *pxt, *pqt, *pkt, *pvp, *ps, *pap;
    cudaGetSymbolAddress(&pwp, g_wp);
    cudaGetSymbolAddress(&pxt, g_xt);
    cudaGetSymbolAddress(&pqt, g_qt);
    cudaGetSymbolAddress(&pkt, g_kt);
    cudaGetSymbolAddress(&pvp, g_vp);
    cudaGetSymbolAddress(&ps,  g_s);
    cudaGetSymbolAddress(&pap, g_ap);
    uint32_t* wp = (uint32_t*)pwp;
    uint32_t* xt = (uint32_t*)pxt;
    uint32_t* qt = (uint32_t*)pqt;
    uint32_t* kt = (uint32_t*)pkt;
    uint32_t* vp = (uint32_t*)pvp;
    float*    sc = (float*)ps;
    uint32_t* ap = (uint32_t*)pap;

    cudaFuncSetAttribute(gemm_kernel<0>, cudaFuncAttributeMaxDynamicSharedMemorySize, GEMM_SMEM);
    cudaFuncSetAttribute(gemm_kernel<1>, cudaFuncAttributeMaxDynamicSharedMemorySize, GEMM_SMEM);
    cudaFuncSetAttribute(gemm_kernel<2>, cudaFuncAttributeMaxDynamicSharedMemorySize, GEMM_SMEM);

    pack_w_kernel<<<CH * CH / 256, 256>>>(wq, wk, wv);
    pack_xt_kernel<<<dim3(NPIX / 32, CH / 32, BATCH), dim3(32, 8)>>>(x);

    // Q^T[n][c] = X^T[n][k] * Wq[c][k]^T  + bq (col bias)
    gemm_kernel<1><<<dim3(1, 32, BATCH), 256, GEMM_SMEM>>>(
        xt, CH, (size_t)NPIX * CH, wp, CH, 0,
        qt, CH, (size_t)NPIX * CH, bq, CH);
    gemm_kernel<1><<<dim3(1, 32, BATCH), 256, GEMM_SMEM>>>(
        xt, CH, (size_t)NPIX * CH, wp + CH * CH, CH, 0,
        kt, CH, (size_t)NPIX * CH, bk, CH);
    // V[c][n] = Wv[c][k] * X^T[n][k]^T  + bv (row bias)
    gemm_kernel<2><<<dim3(NPIX / BN, CH / BM, BATCH), 256, GEMM_SMEM>>>(
        wp + 2 * CH * CH, CH, 0, xt, CH, (size_t)NPIX * CH,
        vp, NPIX, (size_t)CH * NPIX, bv, CH);
    // scores[i][j] = Q^T[i][k] * K^T[j][k]^T
    gemm_kernel<0><<<dim3(NPIX / BN, NPIX / BM, BATCH), 256, GEMM_SMEM>>>(
        qt, CH, (size_t)NPIX * CH, kt, CH, (size_t)NPIX * CH,
        sc, NPIX, (size_t)NPIX * NPIX, nullptr, CH);
    softmax_kernel<<<BATCH * NPIX, 256>>>();
    // out[c][i] = V[c][j] * attn[i][j]^T
    gemm_kernel<0><<<dim3(NPIX / BN, CH / BM, BATCH), 256, GEMM_SMEM>>>(
        vp, NPIX, (size_t)CH * NPIX, ap, NPIX, (size_t)NPIX * NPIX,
        out, NPIX, (size_t)CH * NPIX, nullptr, NPIX);
}

// round 4
// speedup vs baseline: 3.4441x; 1.1763x over previous
#include <cuda_runtime.h>
#include <cuda_bf16.h>
#include <cuda_fp16.h>
#include <math.h>
#include <stdint.h>

#define BATCH 8
#define CH    256
#define NPIX  4096

// Packed split formats: u32 = lo16(hi) | lo16(lo)<<16, value ~= hi + lo
static __device__ uint32_t g_wp[3 * CH * CH];                  // packed bf16 wq|wk|wv
static __device__ uint32_t g_xt[(size_t)BATCH * NPIX * CH];    // x^T  [b][n][c] bf16-split
static __device__ uint32_t g_qt[(size_t)BATCH * NPIX * CH];    // Q^T  [b][n][c] bf16-split
static __device__ uint32_t g_kt[(size_t)BATCH * NPIX * CH];    // K^T  [b][n][c] bf16-split
static __device__ uint32_t g_vp[(size_t)BATCH * CH * NPIX];    // V    [b][c][n] fp16-split
static __device__ float    g_s [(size_t)BATCH * NPIX * NPIX];  // scores fp32
static __device__ __half   g_ah[(size_t)BATCH * NPIX * NPIX];  // attn fp16 [b][i][j]

__device__ __forceinline__ uint32_t smem_u32(const void* p) {
    uint32_t a;
    asm("{ .reg .u64 t; cvta.to.shared.u64 t, %1; cvt.u32.u64 %0, t; }" : "=r"(a) : "l"(p));
    return a;
}
__device__ __forceinline__ uint32_t pack_split(float v) {         // bf16 hi+lo
    __nv_bfloat16 h = __float2bfloat16(v);
    float r = v - __bfloat162float(h);
    __nv_bfloat16 l = __float2bfloat16(r);
    return (uint32_t)__bfloat16_as_ushort(h) | ((uint32_t)__bfloat16_as_ushort(l) << 16);
}
__device__ __forceinline__ uint32_t pack_split_h(float v) {       // fp16 hi+lo
    __half h = __float2half(v);
    float r = v - __half2float(h);
    __half l = __float2half(r);
    return (uint32_t)__half_as_ushort(h) | ((uint32_t)__half_as_ushort(l) << 16);
}
__device__ __forceinline__ void cp16(uint32_t saddr, const void* g) {
    uint64_t ga;
    asm("cvta.to.global.u64 %0, %1;" : "=l"(ga) : "l"(g));
    asm volatile("cp.async.cg.shared.global [%0], [%1], 16;" :: "r"(saddr), "l"(ga));
}
#define CP_COMMIT() asm volatile("cp.async.commit_group;" ::: "memory")
#define CP_WAIT1()  asm volatile("cp.async.wait_group 1;"  ::: "memory")
#define CP_WAIT0()  asm volatile("cp.async.wait_group 0;"  ::: "memory")
#define LDS64(a, b, addr) \
    asm volatile("ld.shared.v2.u32 {%0,%1}, [%2];" : "=r"(a), "=r"(b) : "r"(addr))
#define LDS32(a, addr) \
    asm volatile("ld.shared.u32 %0, [%1];" : "=r"(a) : "r"(addr))
#define MMAB(d, a, b0, b1)                                                        \
    asm volatile("mma.sync.aligned.m16n8k16.row.col.f32.bf16.bf16.f32 "           \
        "{%0,%1,%2,%3}, {%4,%5,%6,%7}, {%8,%9}, {%0,%1,%2,%3};"                   \
        : "+f"((d)[0]), "+f"((d)[1]), "+f"((d)[2]), "+f"((d)[3])                  \
        : "r"((a)[0]), "r"((a)[1]), "r"((a)[2]), "r"((a)[3]), "r"(b0), "r"(b1))
#define MMAH(d, a, b0, b1)                                                        \
    asm volatile("mma.sync.aligned.m16n8k16.row.col.f32.f16.f16.f32 "             \
        "{%0,%1,%2,%3}, {%4,%5,%6,%7}, {%8,%9}, {%0,%1,%2,%3};"                   \
        : "+f"((d)[0]), "+f"((d)[1]), "+f"((d)[2]), "+f"((d)[3])                  \
        : "r"((a)[0]), "r"((a)[1]), "r"((a)[2]), "r"((a)[3]), "r"(b0), "r"(b1))

// ---------------------------------------------------------------------------
// GEMM A: packed split-bf16 both operands, 3-MMA emulation.
// D[M,N] = A[M,K] * B[N,K]^T. CTA 128x256, BK=32, 8 warps, 3-stage cp.async.
// MODE: 0 = fp32 out; 1 = packed bf16-split out + bias[col];
//       2 = packed fp16-split out + bias[row]
// ---------------------------------------------------------------------------
#define BM 128
#define BN 256
#define BK 32
#define A_U32S  (BM * 40)
#define B_U32S  (BN * 40)
#define A_BYTES (A_U32S * 4)
#define BUF_BYTES ((A_U32S + B_U32S) * 4)   // 61440
#define GEMM_SMEM (3 * BUF_BYTES)           // 184320

__device__ __forceinline__ void load_tiles(const uint32_t* __restrict__ Ag, int lda,
                                           const uint32_t* __restrict__ Bg, int ldb,
                                           uint32_t sbase, int tid) {
    #pragma unroll
    for (int i = 0; i < 4; i++) {
        int t = i * 256 + tid;
        int row = t >> 3, q = t & 7;
        cp16(sbase + (uint32_t)(row * 40 + q * 4) * 4, Ag + (size_t)row * lda + q * 4);
    }
    #pragma unroll
    for (int i = 0; i < 8; i++) {
        int t = i * 256 + tid;
        int row = t >> 3, q = t & 7;
        cp16(sbase + A_BYTES + (uint32_t)(row * 40 + q * 4) * 4, Bg + (size_t)row * ldb + q * 4);
    }
}

__device__ __forceinline__ void compute_tile(uint32_t sa, int lane, int wm, int wn,
                                             float (&acc)[4][8][4]) {
    uint32_t sb = sa + A_BYTES;
    #pragma unroll
    for (int ks = 0; ks < 2; ks++) {
        const int kc = ks * 16 + (lane & 3) * 2;
        uint32_t ah[4][4], al[4][4];
        #pragma unroll
        for (int mt = 0; mt < 4; mt++) {
            int r = wm * 64 + mt * 16 + (lane >> 2);
            uint32_t x0, x1, y0, y1, x2, x3, y2, y3;
            LDS64(x0, x1, sa + (uint32_t)(r * 40 + kc) * 4);
            LDS64(y0, y1, sa + (uint32_t)((r + 8) * 40 + kc) * 4);
            LDS64(x2, x3, sa + (uint32_t)(r * 40 + kc + 8) * 4);
            LDS64(y2, y3, sa + (uint32_t)((r + 8) * 40 + kc + 8) * 4);
            ah[mt][0] = __byte_perm(x0, x1, 0x5410); al[mt][0] = __byte_perm(x0, x1, 0x7632);
            ah[mt][1] = __byte_perm(y0, y1, 0x5410); al[mt][1] = __byte_perm(y0, y1, 0x7632);
            ah[mt][2] = __byte_perm(x2, x3, 0x5410); al[mt][2] = __byte_perm(x2, x3, 0x7632);
            ah[mt][3] = __byte_perm(y2, y3, 0x5410); al[mt][3] = __byte_perm(y2, y3, 0x7632);
        }
        #pragma unroll
        for (int nt = 0; nt < 8; nt++) {
            int r = wn * 64 + nt * 8 + (lane >> 2);
            uint32_t u0, u1, u2, u3;
            LDS64(u0, u1, sb + (uint32_t)(r * 40 + kc) * 4);
            LDS64(u2, u3, sb + (uint32_t)(r * 40 + kc + 8) * 4);
            uint32_t bh0 = __byte_perm(u0, u1, 0x5410), bh1 = __byte_perm(u2, u3, 0x5410);
            uint32_t bl0 = __byte_perm(u0, u1, 0x7632), bl1 = __byte_perm(u2, u3, 0x7632);
            #pragma unroll
            for (int mt = 0; mt < 4; mt++) {
                MMAB(acc[mt][nt], ah[mt], bh0, bh1);
                MMAB(acc[mt][nt], ah[mt], bl0, bl1);
                MMAB(acc[mt][nt], al[mt], bh0, bh1);
            }
        }
    }
}

template<int MODE>
__global__ __launch_bounds__(256)
void gemm_kernel(const uint32_t* __restrict__ A, int lda, size_t sA,
                 const uint32_t* __restrict__ B, int ldb, size_t sB,
                 void* __restrict__ Dv, int ldd, size_t sD,
                 const float* __restrict__ bias, int K)
{
    extern __shared__ __align__(16) uint32_t smraw[];
    const uint32_t smbase = smem_u32(smraw);
    const int tid = threadIdx.x;
    const int lane = tid & 31, wid = tid >> 5;
    const int wm = wid >> 2, wn = wid & 3;
    const int z = blockIdx.z;
    const int bm = blockIdx.y * BM, bn = blockIdx.x * BN;

    A += (size_t)z * sA + (size_t)bm * lda;
    B += (size_t)z * sB + (size_t)bn * ldb;

    float acc[4][8][4];
    #pragma unroll
    for (int i = 0; i < 4; i++)
        #pragma unroll
        for (int j = 0; j < 8; j++)
            #pragma unroll
            for (int v = 0; v < 4; v++) acc[i][j][v] = 0.f;

    const int S = K / BK;
    load_tiles(A, lda, B, ldb, smbase, tid);
    CP_COMMIT();
    load_tiles(A + BK, lda, B + BK, ldb, smbase + BUF_BYTES, tid);
    CP_COMMIT();

    #pragma unroll 1
    for (int s = 0; s < S; s++) {
        CP_WAIT1();
        __syncthreads();
        if (s + 2 < S)
            load_tiles(A + (s + 2) * BK, lda, B + (s + 2) * BK, ldb,
                       smbase + (uint32_t)((s + 2) % 3) * BUF_BYTES, tid);
        CP_COMMIT();
        compute_tile(smbase + (uint32_t)(s % 3) * BUF_BYTES, lane, wm, wn, acc);
    }

    #pragma unroll
    for (int nt = 0; nt < 8; nt++) {
        int col = bn + wn * 64 + nt * 8 + (lane & 3) * 2;
        float bc0 = 0.f, bc1 = 0.f;
        if (MODE == 1) { bc0 = bias[col]; bc1 = bias[col + 1]; }
        #pragma unroll
        for (int mt = 0; mt < 4; mt++) {
            int r0 = bm + wm * 64 + mt * 16 + (lane >> 2);
            if (MODE == 0) {
                float* D = (float*)Dv + (size_t)z * sD;
                *(float2*)&D[(size_t)r0 * ldd + col] =
                    make_float2(acc[mt][nt][0], acc[mt][nt][1]);
                *(float2*)&D[(size_t)(r0 + 8) * ldd + col] =
                    make_float2(acc[mt][nt][2], acc[mt][nt][3]);
            } else {
                uint32_t* D = (uint32_t*)Dv + (size_t)z * sD;
                float br0 = bc0, br1 = bc1, br2 = bc0, br3 = bc1;
                if (MODE == 2) {
                    float b0 = bias[r0], b8 = bias[r0 + 8];
                    br0 = b0; br1 = b0; br2 = b8; br3 = b8;
                }
                uint32_t p0, p1, p2, p3;
                if (MODE == 2) {
                    p0 = pack_split_h(acc[mt][nt][0] + br0);
                    p1 = pack_split_h(acc[mt][nt][1] + br1);
                    p2 = pack_split_h(acc[mt][nt][2] + br2);
                    p3 = pack_split_h(acc[mt][nt][3] + br3);
                } else {
                    p0 = pack_split(acc[mt][nt][0] + br0);
                    p1 = pack_split(acc[mt][nt][1] + br1);
                    p2 = pack_split(acc[mt][nt][2] + br2);
                    p3 = pack_split(acc[mt][nt][3] + br3);
                }
                *(uint2*)&D[(size_t)r0 * ldd + col] = make_uint2(p0, p1);
                *(uint2*)&D[(size_t)(r0 + 8) * ldd + col] = make_uint2(p2, p3);
            }
        }
    }
}

// ---------------------------------------------------------------------------
// GEMM B (AV): A = V packed split-fp16 [c][j], B = attn fp16 [i][j].
// D[c][i] fp32. 2-MMA emulation. CTA 128x256, BK=32, 3-stage.
// ---------------------------------------------------------------------------
#define OA_BYTES  (BM * 40 * 4)             // 20480
#define OB_BYTES  (BN * 20 * 4)             // 20480
#define OBUF_BYTES (OA_BYTES + OB_BYTES)    // 40960
#define OUT_SMEM  (3 * OBUF_BYTES)          // 122880

__device__ __forceinline__ void load_tiles_av(const uint32_t* __restrict__ Ag, int lda,
                                              const __half* __restrict__ Bg, int ldb,
                                              uint32_t sbase, int tid) {
    #pragma unroll
    for (int i = 0; i < 4; i++) {
        int t = i * 256 + tid;
        int row = t >> 3, q = t & 7;
        cp16(sbase + (uint32_t)(row * 40 + q * 4) * 4, Ag + (size_t)row * lda + q * 4);
    }
    #pragma unroll
    for (int i = 0; i < 4; i++) {
        int t = i * 256 + tid;
        int row = t >> 2, q = t & 3;
        cp16(sbase + OA_BYTES + (uint32_t)(row * 20 + q * 4) * 4,
             Bg + (size_t)row * ldb + q * 8);
    }
}

__global__ __launch_bounds__(256)
void av_gemm_kernel(const uint32_t* __restrict__ A,   // g_vp
                    const __half* __restrict__ B,      // g_ah
                    float* __restrict__ D)             // out
{
    extern __shared__ __align__(16) uint32_t smraw[];
    const uint32_t smbase = smem_u32(smraw);
    const int tid = threadIdx.x;
    const int lane = tid & 31, wid = tid >> 5;
    const int wm = wid >> 2, wn = wid & 3;
    const int z = blockIdx.z;
    const int bm = blockIdx.y * BM, bn = blockIdx.x * BN;

    A += (size_t)z * CH * NPIX + (size_t)bm * NPIX;
    B += (size_t)z * NPIX * NPIX + (size_t)bn * NPIX;
    D += (size_t)z * CH * NPIX;

    float acc[4][8][4];
    #pragma unroll
    for (int i = 0; i < 4; i++)
        #pragma unroll
        for (int j = 0; j < 8; j++)
            #pragma unroll
            for (int v = 0; v < 4; v++) acc[i][j][v] = 0.f;

    const int S = NPIX / BK;   // 128
    load_tiles_av(A, NPIX, B, NPIX, smbase, tid);
    CP_COMMIT();
    load_tiles_av(A + BK, NPIX, B + BK, NPIX, smbase + OBUF_BYTES, tid);
    CP_COMMIT();

    #pragma unroll 1
    for (int s = 0; s < S; s++) {
        CP_WAIT1();
        __syncthreads();
        if (s + 2 < S)
            load_tiles_av(A + (s + 2) * BK, NPIX, B + (s + 2) * BK, NPIX,
                          smbase + (uint32_t)((s + 2) % 3) * OBUF_BYTES, tid);
        CP_COMMIT();

        uint32_t sa = smbase + (uint32_t)(s % 3) * OBUF_BYTES;
        uint32_t sb = sa + OA_BYTES;
        #pragma unroll
        for (int ks = 0; ks < 2; ks++) {
            const int kc = ks * 16 + (lane & 3) * 2;   // u32 col in A tile
            uint32_t ah[4][4], al[4][4];
            #pragma unroll
            for (int mt = 0; mt < 4; mt++) {
                int r = wm * 64 + mt * 16 + (lane >> 2);
                uint32_t x0, x1, y0, y1, x2, x3, y2, y3;
                LDS64(x0, x1, sa + (uint32_t)(r * 40 + kc) * 4);
                LDS64(y0, y1, sa + (uint32_t)((r + 8) * 40 + kc) * 4);
                LDS64(x2, x3, sa + (uint32_t)(r * 40 + kc + 8) * 4);
                LDS64(y2, y3, sa + (uint32_t)((r + 8) * 40 + kc + 8) * 4);
                ah[mt][0] = __byte_perm(x0, x1, 0x5410); al[mt][0] = __byte_perm(x0, x1, 0x7632);
                ah[mt][1] = __byte_perm(y0, y1, 0x5410); al[mt][1] = __byte_perm(y0, y1, 0x7632);
                ah[mt][2] = __byte_perm(x2, x3, 0x5410); al[mt][2] = __byte_perm(x2, x3, 0x7632);
                ah[mt][3] = __byte_perm(y2, y3, 0x5410); al[mt][3] = __byte_perm(y2, y3, 0x7632);
            }
            const int bkc = ks * 8 + (lane & 3);       // u32 col in B tile (fp16 pairs)
            #pragma unroll
            for (int nt = 0; nt < 8; nt++) {
                int r = wn * 64 + nt * 8 + (lane >> 2);
                uint32_t b0, b1;
                LDS32(b0, sb + (uint32_t)(r * 20 + bkc) * 4);
                LDS32(b1, sb + (uint32_t)(r * 20 + bkc + 4) * 4);
                #pragma unroll
                for (int mt = 0; mt < 4; mt++) {
                    MMAH(acc[mt][nt], ah[mt], b0, b1);
                    MMAH(acc[mt][nt], al[mt], b0, b1);
                }
            }
        }
    }

    #pragma unroll
    for (int nt = 0; nt < 8; nt++) {
        int col = bn + wn * 64 + nt * 8 + (lane & 3) * 2;
        #pragma unroll
        for (int mt = 0; mt < 4; mt++) {
            int r0 = bm + wm * 64 + mt * 16 + (lane >> 2);
            *(float2*)&D[(size_t)r0 * NPIX + col] =
                make_float2(acc[mt][nt][0], acc[mt][nt][1]);
            *(float2*)&D[(size_t)(r0 + 8) * NPIX + col] =
                make_float2(acc[mt][nt][2], acc[mt][nt][3]);
        }
    }
}

// ---------------------------------------------------------------------------
// Packing kernels
// ---------------------------------------------------------------------------
__global__ __launch_bounds__(256) void pack_w_kernel(
    const float* __restrict__ wq, const float* __restrict__ wk,
    const float* __restrict__ wv)
{
    int i = blockIdx.x * 256 + threadIdx.x;
    g_wp[i]               = pack_split(wq[i]);
    g_wp[CH * CH + i]     = pack_split(wk[i]);
    g_wp[2 * CH * CH + i] = pack_split(wv[i]);
}

__global__ __launch_bounds__(256) void pack_xt_kernel(const float* __restrict__ x)
{
    __shared__ float t[32][33];
    const int b = blockIdx.z;
    const int n0 = blockIdx.x * 32, c0 = blockIdx.y * 32;
    const int tx = threadIdx.x, ty = threadIdx.y;   // 32 x 8
    const float* xb = x + (size_t)b * CH * NPIX;
    #pragma unroll
    for (int i = 0; i < 4; i++)
        t[ty * 4 + i][tx] = xb[(size_t)(c0 + ty * 4 + i) * NPIX + n0 + tx];
    __syncthreads();
    uint32_t* xt = g_xt + (size_t)b * NPIX * CH;
    #pragma unroll
    for (int i = 0; i < 4; i++)
        xt[(size_t)(n0 + ty * 4 + i) * CH + c0 + tx] = pack_split(t[tx][ty * 4 + i]);
}

// ---------------------------------------------------------------------------
// Softmax: fp32 scores -> fp16 attn
// ---------------------------------------------------------------------------
__global__ __launch_bounds__(256) void softmax_kernel()
{
    const float* row = g_s + (size_t)blockIdx.x * NPIX;
    __half* orow = g_ah + (size_t)blockIdx.x * NPIX;
    const int tid = threadIdx.x;

    float v[16];
    float mx = -1e30f;
    #pragma unroll
    for (int i = 0; i < 16; i++) {
        v[i] = row[tid + 256 * i];
        mx = fmaxf(mx, v[i]);
    }
    __shared__ float red[8];
    #pragma unroll
    for (int o = 16; o > 0; o >>= 1)
        mx = fmaxf(mx, __shfl_xor_sync(0xffffffffu, mx, o));
    if ((tid & 31) == 0) red[tid >> 5] = mx;
    __syncthreads();
    float bm = red[0];
    #pragma unroll
    for (int i = 1; i < 8; i++) bm = fmaxf(bm, red[i]);
    __syncthreads();

    float sum = 0.f;
    #pragma unroll
    for (int i = 0; i < 16; i++) {
        v[i] = expf(v[i] - bm);
        sum += v[i];
    }
    #pragma unroll
    for (int o = 16; o > 0; o >>= 1)
        sum += __shfl_xor_sync(0xffffffffu, sum, o);
    if ((tid & 31) == 0) red[tid >> 5] = sum;
    __syncthreads();
    float tot = 0.f;
    #pragma unroll
    for (int i = 0; i < 8; i++) tot += red[i];
    float inv = 1.0f / tot;

    #pragma unroll
    for (int i = 0; i < 16; i++)
        orow[tid + 256 * i] = __float2half(v[i] * inv);
}

// ---------------------------------------------------------------------------
extern "C" void kernel_launch(void* const* d_in, const int* in_sizes, int n_in,
                              void* d_out, int out_size)
{
    const float* x  = (const float*)d_in[0];
    const float* wq = (const float*)d_in[1];
    const float* bq = (const float*)d_in[2];
    const float* wk = (const float*)d_in[3];
    const float* bk = (const float*)d_in[4];
    const float* wv = (const float*)d_in[5];
    const float* bv = (const float*)d_in[6];
    float* out = (float*)d_out;

    void *pwp, *pxt, *pqt, *pkt, *pvp, *ps, *pah;
    cudaGetSymbolAddress(&pwp, g_wp);
    cudaGetSymbolAddress(&pxt, g_xt);
    cudaGetSymbolAddress(&pqt, g_qt);
    cudaGetSymbolAddress(&pkt, g_kt);
    cudaGetSymbolAddress(&pvp, g_vp);
    cudaGetSymbolAddress(&ps,  g_s);
    cudaGetSymbolAddress(&pah, g_ah);
    uint32_t* wp = (uint32_t*)pwp;
    uint32_t* xt = (uint32_t*)pxt;
    uint32_t* qt = (uint32_t*)pqt;
    uint32_t* kt = (uint32_t*)pkt;
    uint32_t* vp = (uint32_t*)pvp;
    float*    sc = (float*)ps;
    __half*   ah = (__half*)pah;

    cudaFuncSetAttribute(gemm_kernel<0>, cudaFuncAttributeMaxDynamicSharedMemorySize, GEMM_SMEM);
    cudaFuncSetAttribute(gemm_kernel<1>, cudaFuncAttributeMaxDynamicSharedMemorySize, GEMM_SMEM);
    cudaFuncSetAttribute(gemm_kernel<2>, cudaFuncAttributeMaxDynamicSharedMemorySize, GEMM_SMEM);
    cudaFuncSetAttribute(av_gemm_kernel, cudaFuncAttributeMaxDynamicSharedMemorySize, OUT_SMEM);

    pack_w_kernel<<<CH * CH / 256, 256>>>(wq, wk, wv);
    pack_xt_kernel<<<dim3(NPIX / 32, CH / 32, BATCH), dim3(32, 8)>>>(x);

    // Q^T[n][c] = X^T[n][k] * Wq[c][k]^T + bq (col bias)
    gemm_kernel<1><<<dim3(1, 32, BATCH), 256, GEMM_SMEM>>>(
        xt, CH, (size_t)NPIX * CH, wp, CH, 0,
        qt, CH, (size_t)NPIX * CH, bq, CH);
    gemm_kernel<1><<<dim3(1, 32, BATCH), 256, GEMM_SMEM>>>(
        xt, CH, (size_t)NPIX * CH, wp + CH * CH, CH, 0,
        kt, CH, (size_t)NPIX * CH, bk, CH);
    // V[c][n] = Wv[c][k] * X^T[n][k]^T + bv (row bias) -> fp16-split pack
    gemm_kernel<2><<<dim3(NPIX / BN, CH / BM, BATCH), 256, GEMM_SMEM>>>(
        wp + 2 * CH * CH, CH, 0, xt, CH, (size_t)NPIX * CH,
        vp, NPIX, (size_t)CH * NPIX, bv, CH);
    // scores[i][j] = Q^T[i][k] * K^T[j][k]^T
    gemm_kernel<0><<<dim3(NPIX / BN, NPIX / BM, BATCH), 256, GEMM_SMEM>>>(
        qt, CH, (size_t)NPIX * CH, kt, CH, (size_t)NPIX * CH,
        sc, NPIX, (size_t)NPIX * NPIX, nullptr, CH);
    softmax_kernel<<<BATCH * NPIX, 256>>>();
    // out[c][i] = V[c][j] * attn[i][j]^T
    av_gemm_kernel<<<dim3(NPIX / BN, CH / BM, BATCH), 256, OUT_SMEM>>>(vp, ah, out);
}